// round 9
// baseline (speedup 1.0000x reference)
#include <cuda_runtime.h>
#include <math.h>
#include <stdint.h>

#define S_LEN 2048
#define DM    2048
#define QH    32
#define KVH   8
#define DH    64
#define KV_W  (2 * KVH * DH)   // 1024

// ---------------- scratch (allocation-free: __device__ globals) ----------------
__device__ float g_Qf[S_LEN * DM];          // fp32 Q proj (pre-rope)
__device__ float g_KVf[S_LEN * KV_W];       // fp32 KV proj
__device__ uint2 g_xp[S_LEN * DM / 2];      // packed x
__device__ uint2 g_Wqp[DM * DM / 2];        // packed W_q
__device__ uint2 g_Wkvp[KV_W * DM / 2];     // packed W_kv
__device__ uint2 g_Wop[DM * DM / 2];        // packed W_out
__device__ uint2 g_Qp[S_LEN * DM / 2];      // packed rope'd scaled Q
__device__ uint2 g_Kp[S_LEN * KVH * DH / 2];// packed rope'd K
__device__ uint2 g_Vtp[KVH * DH * S_LEN / 2];// packed V^T (pairs along seq)
__device__ uint2 g_attnp[S_LEN * DM / 2];   // packed attention output
__device__ float g_freq[32];

// ============================ helpers ====================================
__device__ __forceinline__ uint32_t smem_u32(const void* p) {
    uint32_t a;
    asm("{ .reg .u64 t; cvta.to.shared.u64 t, %1; cvt.u32.u64 %0, t; }" : "=r"(a) : "l"(p));
    return a;
}
#define CP_ASYNC16(dst, src) \
    asm volatile("cp.async.cg.shared.global [%0], [%1], 16;" :: "r"(dst), "l"(src))
#define CP_COMMIT() asm volatile("cp.async.commit_group;" ::: "memory")
#define CP_WAIT1()  asm volatile("cp.async.wait_group 1;" ::: "memory")
#define CP_WAIT0()  asm volatile("cp.async.wait_group 0;" ::: "memory")

__device__ __forceinline__ uint32_t pack_bf16(float f1_hi, float f0_lo) {
    uint32_t d;
    asm("cvt.rn.bf16x2.f32 %0, %1, %2;" : "=r"(d) : "f"(f1_hi), "f"(f0_lo));
    return d;
}
__device__ __forceinline__ void split2(float f0, float f1, uint32_t& h, uint32_t& l) {
    h = pack_bf16(f1, f0);
    float h0 = __uint_as_float(h << 16);
    float h1 = __uint_as_float(h & 0xFFFF0000u);
    l = pack_bf16(f1 - h1, f0 - h0);
}
__device__ __forceinline__ void mma_bf16(float* d,
                                         uint32_t a0, uint32_t a1, uint32_t a2, uint32_t a3,
                                         uint32_t b0, uint32_t b1) {
    asm volatile(
        "mma.sync.aligned.m16n8k16.row.col.f32.bf16.bf16.f32 "
        "{%0,%1,%2,%3}, {%4,%5,%6,%7}, {%8,%9}, {%0,%1,%2,%3};"
        : "+f"(d[0]), "+f"(d[1]), "+f"(d[2]), "+f"(d[3])
        : "r"(a0), "r"(a1), "r"(a2), "r"(a3), "r"(b0), "r"(b1));
}

// ==============================================================================
// pre-pack: fp32 pairs -> {hi bf16x2, lo bf16x2}
// ==============================================================================
__global__ void pack_pairs(const float2* __restrict__ in, uint2* __restrict__ out, int n2)
{
    int i = blockIdx.x * blockDim.x + threadIdx.x;
    if (i >= n2) return;
    float2 f = in[i];
    uint2 o;
    split2(f.x, f.y, o.x, o.y);
    out[i] = o;
}

// ==============================================================================
// 3xBF16 GEMM, packed operands: C[M,N] = A[M,K] @ B[N,K]^T + bias[N]
// 128x128 CTA tile, BK=32, 256 threads (8 warps, 32x64 warp tiles).
// smem: 2 stages of packed A[128][16u2]+B[128][16u2], row stride 20 uint2.
// Mainloop: pure LDS.64 + MMA, zero conversions.
// ==============================================================================
#define GST      20                    // uint2 per row (16 data + 4 pad)
#define GTILE_U  (128 * GST)           // 2560 uint2 per tile
#define GTILE_B  (GTILE_U * 8)         // 20480 bytes
#define GSTAGE_U (2 * GTILE_U)         // A+B
#define GSTAGE_B (2 * GTILE_B)         // 40960
#define TG_SMEM  (2 * GSTAGE_B)        // 81920

__global__ __launch_bounds__(256, 2)
void tgemm_bf16p(const uint2* __restrict__ A, const uint2* __restrict__ B,
                 const float* __restrict__ bias, float* __restrict__ C,
                 int M, int N, int K)
{
    extern __shared__ uint2 smu[];
    const uint32_t smb = smem_u32(smu);

    const int tid  = threadIdx.x;
    const int wid  = tid >> 5;
    const int lane = tid & 31;
    const int qr   = lane >> 2;
    const int qc   = lane & 3;
    const int wm   = (wid & 3) * 32;
    const int wn   = (wid >> 2) * 64;
    const int brow = blockIdx.y * 128;
    const int bcol = blockIdx.x * 128;
    const int ldu  = K >> 1;

    // loader: thread owns one row of A or B (128 B data per stage)
    const int lrow = tid & 127;
    const uint2* src0 = (tid < 128) ? (A + (size_t)(brow + lrow) * ldu)
                                    : (B + (size_t)(bcol + lrow) * ldu);
    const uint32_t dbase = smb + ((tid < 128) ? 0u : (uint32_t)GTILE_B) + (uint32_t)lrow * 160;

    const int NT = K >> 5;

    auto issue = [&](int kt) {
        const uint2* s = src0 + kt * 16;
        uint32_t d = dbase + (uint32_t)(kt & 1) * GSTAGE_B;
#pragma unroll
        for (int j = 0; j < 8; j++) CP_ASYNC16(d + 16 * j, s + 2 * j);
    };

    float acc[2][8][4];
#pragma unroll
    for (int mt = 0; mt < 2; mt++)
#pragma unroll
        for (int nt = 0; nt < 8; nt++)
#pragma unroll
            for (int i = 0; i < 4; i++) acc[mt][nt][i] = 0.0f;

    issue(0); CP_COMMIT();
    issue(1); CP_COMMIT();

    for (int kt = 0; kt < NT; kt++) {
        CP_WAIT1();
        __syncthreads();

        const uint2* As = smu + (kt & 1) * GSTAGE_U;
        const uint2* Bs = As + GTILE_U;

#pragma unroll
        for (int ks = 0; ks < 2; ks++) {
            uint2 bf[8][2];
#pragma unroll
            for (int nt = 0; nt < 8; nt++) {
                const int o = (wn + nt * 8 + qr) * GST + ks * 8 + qc;
                bf[nt][0] = Bs[o];
                bf[nt][1] = Bs[o + 4];
            }
#pragma unroll
            for (int mt = 0; mt < 2; mt++) {
                const int o = (wm + mt * 16 + qr) * GST + ks * 8 + qc;
                uint2 a0 = As[o];
                uint2 a1 = As[o + 8 * GST];
                uint2 a2 = As[o + 4];
                uint2 a3 = As[o + 8 * GST + 4];
#pragma unroll
                for (int nt = 0; nt < 8; nt++) {
                    mma_bf16(acc[mt][nt], a0.x, a1.x, a2.x, a3.x, bf[nt][0].x, bf[nt][1].x);
                    mma_bf16(acc[mt][nt], a0.x, a1.x, a2.x, a3.x, bf[nt][0].y, bf[nt][1].y);
                    mma_bf16(acc[mt][nt], a0.y, a1.y, a2.y, a3.y, bf[nt][0].x, bf[nt][1].x);
                }
            }
        }
        __syncthreads();
        if (kt + 2 < NT) issue(kt + 2);
        CP_COMMIT();
    }

#pragma unroll
    for (int mt = 0; mt < 2; mt++) {
        const int row = brow + wm + mt * 16 + qr;
#pragma unroll
        for (int nt = 0; nt < 8; nt++) {
            const int col = bcol + wn + nt * 8 + qc * 2;
            const float b0 = bias[col], b1 = bias[col + 1];
            *(float2*)(C + (size_t)row * N + col) =
                make_float2(acc[mt][nt][0] + b0, acc[mt][nt][1] + b1);
            *(float2*)(C + (size_t)(row + 8) * N + col) =
                make_float2(acc[mt][nt][2] + b0, acc[mt][nt][3] + b1);
        }
    }
}

// ==============================================================================
// RoPE + pack: reads fp32 proj, writes packed rope'd {hi,lo}. scale folds 1/8.
// ==============================================================================
__global__ void freq_kernel()
{
    int j = threadIdx.x;
    if (j < 32) g_freq[j] = (float)pow(10000.0, -(double)j / 32.0);
}

__global__ void ropepack_kernel(const float* __restrict__ X, uint2* __restrict__ out,
                                int H, int istride, int ostride, float scale)
{
    int idx = blockIdx.x * blockDim.x + threadIdx.x;
    int total = S_LEN * H * (DH / 2);
    if (idx >= total) return;

    int j = idx & 31;
    int t = idx >> 5;
    int h = t % H;
    int s = t / H;

    float theta = (float)s * g_freq[j];
    float sn, cs;
    sincosf(theta, &sn, &cs);

    const float* p = X + (size_t)s * istride + h * DH + 2 * j;
    float x1 = p[0], x2 = p[1];
    float o1 = (x1 * cs - x2 * sn) * scale;
    float o2 = (x1 * sn + x2 * cs) * scale;
    uint2 o;
    split2(o1, o2, o.x, o.y);
    out[(size_t)s * ostride + h * (DH / 2) + j] = o;
}

// V^T pack: g_Vtp[hk][d][sp] = split(V[2sp][hk,d], V[2sp+1][hk,d])
__global__ void vtpack_kernel(const float* __restrict__ KV, uint2* __restrict__ Vt)
{
    int idx = blockIdx.x * blockDim.x + threadIdx.x;   // hk*65536 + d*1024 + sp
    if (idx >= KVH * DH * (S_LEN / 2)) return;
    int sp = idx & (S_LEN / 2 - 1);
    int d  = (idx >> 10) & (DH - 1);
    int hk = idx >> 16;
    const float* base = KV + (size_t)(2 * sp) * KV_W + KVH * DH + hk * DH + d;
    float v0 = base[0];
    float v1 = base[KV_W];
    uint2 o;
    split2(v0, v1, o.x, o.y);
    Vt[idx] = o;
}

// ==============================================================================
// Flash attention, fully packed operands. Block = (128 q-rows, head).
// 128 threads = 4 warps; warp owns 32 rows. smem stride 36 uint2 (proven
// conflict-free). Epilogue writes packed output for the out-projection.
// ==============================================================================
#define AST 36                                   // uint2 stride
#define OFF_P (128 * AST * 8)                    // 36864
#define OFF_K (2 * OFF_P)                        // 73728
#define OFF_V (OFF_K + 64 * AST * 8)             // 92160
#define FA_SMEM (OFF_V + 64 * AST * 8)           // 110592

__global__ __launch_bounds__(128, 2)
void flash_attn_p(const uint2* __restrict__ Qp, const uint2* __restrict__ Kp,
                  const uint2* __restrict__ Vtp, uint2* __restrict__ Op)
{
    extern __shared__ char smc[];
    const uint32_t smb = smem_u32(smc);
    uint2* Qsm = (uint2*)smc;
    uint2* Psm = (uint2*)(smc + OFF_P);
    uint2* Ksm = (uint2*)(smc + OFF_K);
    uint2* Vsm = (uint2*)(smc + OFF_V);

    const int qt   = blockIdx.x;
    const int h    = blockIdx.y;
    const int hk   = h >> 2;
    const int tid  = threadIdx.x;
    const int wid  = tid >> 5;
    const int lane = tid & 31;
    const int qr   = lane >> 2;
    const int qc   = lane & 3;
    const int wm   = wid * 32;

    // ---- prologue: cp.async Q tile (128 rows x 256B) ----
    {
        const uint2* src = Qp + (size_t)(qt * 128 + tid) * (DM / 2) + h * (DH / 2);
        uint32_t dst = smb + (uint32_t)tid * (AST * 8);
#pragma unroll
        for (int j = 0; j < 16; j++) CP_ASYNC16(dst + 16 * j, src + 2 * j);
    }

    float m_i[2][2], l_i[2][2];
#pragma unroll
    for (int mt = 0; mt < 2; mt++)
#pragma unroll
        for (int hf = 0; hf < 2; hf++) { m_i[mt][hf] = -1e30f; l_i[mt][hf] = 0.0f; }

    float acc[2][8][4];
#pragma unroll
    for (int mt = 0; mt < 2; mt++)
#pragma unroll
        for (int nt = 0; nt < 8; nt++)
#pragma unroll
            for (int i = 0; i < 4; i++) acc[mt][nt][i] = 0.0f;

    for (int kt = 0; kt < 32; kt++) {
        __syncthreads();   // previous compute done reading K/V

        // ---- cp.async K tile (64 keys x 256B) and Vt tile (64 dims x 256B) ----
        {
            const int row  = tid >> 1;
            const int half = tid & 1;
            const uint2* kg = Kp + (size_t)(kt * 64 + row) * (KVH * DH / 2) + hk * (DH / 2) + half * 16;
            const uint2* vg = Vtp + (size_t)(hk * 64 + row) * (S_LEN / 2) + kt * 32 + half * 16;
            uint32_t kd = smb + OFF_K + (uint32_t)row * (AST * 8) + half * 128;
            uint32_t vd = smb + OFF_V + (uint32_t)row * (AST * 8) + half * 128;
#pragma unroll
            for (int j = 0; j < 8; j++) {
                CP_ASYNC16(kd + 16 * j, kg + 2 * j);
                CP_ASYNC16(vd + 16 * j, vg + 2 * j);
            }
        }
        CP_COMMIT();
        CP_WAIT0();
        __syncthreads();

        // ---- S = Q @ K^T (3xBF16, zero conversions) ----
        float s[2][8][4];
#pragma unroll
        for (int mt = 0; mt < 2; mt++)
#pragma unroll
            for (int nt = 0; nt < 8; nt++)
#pragma unroll
                for (int i = 0; i < 4; i++) s[mt][nt][i] = 0.0f;

#pragma unroll
        for (int ks = 0; ks < 4; ks++) {
            uint2 bk[8][2];
#pragma unroll
            for (int nt = 0; nt < 8; nt++) {
                const int o = (nt * 8 + qr) * AST + ks * 8 + qc;
                bk[nt][0] = Ksm[o];
                bk[nt][1] = Ksm[o + 4];
            }
#pragma unroll
            for (int mt = 0; mt < 2; mt++) {
                const int o = (wm + mt * 16 + qr) * AST + ks * 8 + qc;
                uint2 a0 = Qsm[o];
                uint2 a1 = Qsm[o + 8 * AST];
                uint2 a2 = Qsm[o + 4];
                uint2 a3 = Qsm[o + 8 * AST + 4];
#pragma unroll
                for (int nt = 0; nt < 8; nt++) {
                    mma_bf16(s[mt][nt], a0.x, a1.x, a2.x, a3.x, bk[nt][0].x, bk[nt][1].x);
                    mma_bf16(s[mt][nt], a0.x, a1.x, a2.x, a3.x, bk[nt][0].y, bk[nt][1].y);
                    mma_bf16(s[mt][nt], a0.y, a1.y, a2.y, a3.y, bk[nt][0].x, bk[nt][1].x);
                }
            }
        }

        // ---- online softmax ----
#pragma unroll
        for (int mt = 0; mt < 2; mt++) {
#pragma unroll
            for (int hf = 0; hf < 2; hf++) {
                float mx = -1e30f;
#pragma unroll
                for (int nt = 0; nt < 8; nt++)
                    mx = fmaxf(mx, fmaxf(s[mt][nt][2 * hf], s[mt][nt][2 * hf + 1]));
                mx = fmaxf(mx, __shfl_xor_sync(0xffffffffu, mx, 1));
                mx = fmaxf(mx, __shfl_xor_sync(0xffffffffu, mx, 2));
                float m_new = fmaxf(m_i[mt][hf], mx);
                float alpha = __expf(m_i[mt][hf] - m_new);
                float rs = 0.0f;
#pragma unroll
                for (int nt = 0; nt < 8; nt++) {
                    s[mt][nt][2 * hf]     = __expf(s[mt][nt][2 * hf] - m_new);
                    s[mt][nt][2 * hf + 1] = __expf(s[mt][nt][2 * hf + 1] - m_new);
                    rs += s[mt][nt][2 * hf] + s[mt][nt][2 * hf + 1];
                }
                rs += __shfl_xor_sync(0xffffffffu, rs, 1);
                rs += __shfl_xor_sync(0xffffffffu, rs, 2);
                l_i[mt][hf] = l_i[mt][hf] * alpha + rs;
                m_i[mt][hf] = m_new;
#pragma unroll
                for (int nt = 0; nt < 8; nt++) {
                    acc[mt][nt][2 * hf]     *= alpha;
                    acc[mt][nt][2 * hf + 1] *= alpha;
                }
            }
        }

        // ---- write P packed (warp-private rows) ----
#pragma unroll
        for (int mt = 0; mt < 2; mt++) {
            const int r0 = (wm + mt * 16 + qr) * AST;
#pragma unroll
            for (int nt = 0; nt < 8; nt++) {
                uint2 o;
                split2(s[mt][nt][0], s[mt][nt][1], o.x, o.y);
                Psm[r0 + nt * 4 + qc] = o;
                split2(s[mt][nt][2], s[mt][nt][3], o.x, o.y);
                Psm[r0 + 8 * AST + nt * 4 + qc] = o;
            }
        }
        __syncwarp();

        // ---- acc += P @ V (3xBF16, V^T pre-packed) ----
#pragma unroll
        for (int ks = 0; ks < 4; ks++) {
            uint2 bv[8][2];
#pragma unroll
            for (int nt = 0; nt < 8; nt++) {
                const int o = (nt * 8 + qr) * AST + ks * 8 + qc;
                bv[nt][0] = Vsm[o];
                bv[nt][1] = Vsm[o + 4];
            }
#pragma unroll
            for (int mt = 0; mt < 2; mt++) {
                const int o = (wm + mt * 16 + qr) * AST + ks * 8 + qc;
                uint2 p0 = Psm[o];
                uint2 p1 = Psm[o + 8 * AST];
                uint2 p2 = Psm[o + 4];
                uint2 p3 = Psm[o + 8 * AST + 4];
#pragma unroll
                for (int nt = 0; nt < 8; nt++) {
                    mma_bf16(acc[mt][nt], p0.x, p1.x, p2.x, p3.x, bv[nt][0].x, bv[nt][1].x);
                    mma_bf16(acc[mt][nt], p0.x, p1.x, p2.x, p3.x, bv[nt][0].y, bv[nt][1].y);
                    mma_bf16(acc[mt][nt], p0.y, p1.y, p2.y, p3.y, bv[nt][0].x, bv[nt][1].x);
                }
            }
        }
    }

    // ---- epilogue: normalize, pack, store ----
#pragma unroll
    for (int mt = 0; mt < 2; mt++) {
        const float i0 = 1.0f / l_i[mt][0];
        const float i1 = 1.0f / l_i[mt][1];
        const int row = qt * 128 + wm + mt * 16 + qr;
#pragma unroll
        for (int nt = 0; nt < 8; nt++) {
            uint2 o;
            size_t idx0 = (size_t)row * (DM / 2) + h * (DH / 2) + nt * 4 + qc;
            split2(acc[mt][nt][0] * i0, acc[mt][nt][1] * i0, o.x, o.y);
            Op[idx0] = o;
            split2(acc[mt][nt][2] * i1, acc[mt][nt][3] * i1, o.x, o.y);
            Op[idx0 + 8 * (DM / 2)] = o;
        }
    }
}

// ==============================================================================
// launch
// ==============================================================================
extern "C" void kernel_launch(void* const* d_in, const int* in_sizes, int n_in,
                              void* d_out, int out_size)
{
    const float* x     = (const float*)d_in[0];
    const float* W_q   = (const float*)d_in[1];
    const float* b_q   = (const float*)d_in[2];
    const float* W_kv  = (const float*)d_in[3];
    const float* b_kv  = (const float*)d_in[4];
    const float* W_out = (const float*)d_in[5];
    const float* b_out = (const float*)d_in[6];
    float* out = (float*)d_out;

    float *qf, *kvf;
    uint2 *xp, *wqp, *wkvp, *wop, *qp, *kp, *vtp, *ap;
    cudaGetSymbolAddress((void**)&qf,  g_Qf);
    cudaGetSymbolAddress((void**)&kvf, g_KVf);
    cudaGetSymbolAddress((void**)&xp,  g_xp);
    cudaGetSymbolAddress((void**)&wqp, g_Wqp);
    cudaGetSymbolAddress((void**)&wkvp, g_Wkvp);
    cudaGetSymbolAddress((void**)&wop, g_Wop);
    cudaGetSymbolAddress((void**)&qp,  g_Qp);
    cudaGetSymbolAddress((void**)&kp,  g_Kp);
    cudaGetSymbolAddress((void**)&vtp, g_Vtp);
    cudaGetSymbolAddress((void**)&ap,  g_attnp);

    cudaFuncSetAttribute(flash_attn_p, cudaFuncAttributeMaxDynamicSharedMemorySize, FA_SMEM);
    cudaFuncSetAttribute(tgemm_bf16p, cudaFuncAttributeMaxDynamicSharedMemorySize, TG_SMEM);

    // 0: freq table
    freq_kernel<<<1, 32>>>();
    // 1-4: pack inputs
    pack_pairs<<<(S_LEN * DM / 2 + 255) / 256, 256>>>((const float2*)x, xp, S_LEN * DM / 2);
    pack_pairs<<<(DM * DM / 2 + 255) / 256, 256>>>((const float2*)W_q, wqp, DM * DM / 2);
    pack_pairs<<<(KV_W * DM / 2 + 255) / 256, 256>>>((const float2*)W_kv, wkvp, KV_W * DM / 2);
    pack_pairs<<<(DM * DM / 2 + 255) / 256, 256>>>((const float2*)W_out, wop, DM * DM / 2);

    // 5: Q projection (ncu -s 5 captures this one)
    tgemm_bf16p<<<dim3(DM / 128, S_LEN / 128), 256, TG_SMEM>>>(
        xp, wqp, b_q, qf, S_LEN, DM, DM);
    // 6: KV projection
    tgemm_bf16p<<<dim3(KV_W / 128, S_LEN / 128), 256, TG_SMEM>>>(
        xp, wkvp, b_kv, kvf, S_LEN, KV_W, DM);

    // 7-9: rope+pack Q, K; transpose+pack V
    ropepack_kernel<<<(S_LEN * QH * 32 + 255) / 256, 256>>>(qf, qp, QH, DM, DM / 2, 0.125f);
    ropepack_kernel<<<(S_LEN * KVH * 32 + 255) / 256, 256>>>(kvf, kp, KVH, KV_W, KVH * DH / 2, 1.0f);
    vtpack_kernel<<<(KVH * DH * S_LEN / 2 + 255) / 256, 256>>>(kvf, vtp);

    // 10: flash attention (packed in/out)
    flash_attn_p<<<dim3(S_LEN / 128, QH), 128, FA_SMEM>>>(qp, kp, vtp, ap);

    // 11: output projection
    tgemm_bf16p<<<dim3(DM / 128, S_LEN / 128), 256, TG_SMEM>>>(
        ap, wop, b_out, out, S_LEN, DM, DM);
}

// round 10
// speedup vs baseline: 1.0229x; 1.0229x over previous
#include <cuda_runtime.h>
#include <math.h>
#include <stdint.h>

#define S_LEN 2048
#define DM    2048
#define QH    32
#define KVH   8
#define DH    64
#define KV_W  (2 * KVH * DH)   // 1024

// ---------------- scratch (allocation-free: __device__ globals) ----------------
__device__ float g_Qf[S_LEN * DM];           // 16 MB fp32 Q proj (pre-rope)
__device__ float g_KVf[S_LEN * KV_W];        //  8 MB fp32 KV proj
__device__ uint2 g_Qp[S_LEN * DM / 2];       // 16 MB packed rope'd scaled Q
__device__ uint2 g_Kp[S_LEN * KVH * DH / 2]; //  4 MB packed rope'd K
__device__ uint2 g_Vtp[KVH * DH * S_LEN / 2];//  4 MB packed V^T (pairs along seq)
__device__ float g_attn[S_LEN * DM];         // 16 MB fp32 attention output

// ============================ helpers ====================================
__device__ __forceinline__ uint32_t smem_u32(const void* p) {
    uint32_t a;
    asm("{ .reg .u64 t; cvta.to.shared.u64 t, %1; cvt.u32.u64 %0, t; }" : "=r"(a) : "l"(p));
    return a;
}
#define CP_ASYNC16(dst, src) \
    asm volatile("cp.async.cg.shared.global [%0], [%1], 16;" :: "r"(dst), "l"(src))
#define CP_COMMIT() asm volatile("cp.async.commit_group;" ::: "memory")
#define CP_WAIT1()  asm volatile("cp.async.wait_group 1;" ::: "memory")

__device__ __forceinline__ uint32_t pack_bf16(float f1_hi, float f0_lo) {
    uint32_t d;
    asm("cvt.rn.bf16x2.f32 %0, %1, %2;" : "=r"(d) : "f"(f1_hi), "f"(f0_lo));
    return d;
}
// round-to-nearest hi/lo split of a pair: f = hi + lo, |lo| <= 2^-8 |f|
__device__ __forceinline__ void split2(float f0, float f1, uint32_t& h, uint32_t& l) {
    h = pack_bf16(f1, f0);
    float h0 = __uint_as_float(h << 16);
    float h1 = __uint_as_float(h & 0xFFFF0000u);
    l = pack_bf16(f1 - h1, f0 - h0);
}
__device__ __forceinline__ void mma_bf16(float* d,
                                         uint32_t a0, uint32_t a1, uint32_t a2, uint32_t a3,
                                         uint32_t b0, uint32_t b1) {
    asm volatile(
        "mma.sync.aligned.m16n8k16.row.col.f32.bf16.bf16.f32 "
        "{%0,%1,%2,%3}, {%4,%5,%6,%7}, {%8,%9}, {%0,%1,%2,%3};"
        : "+f"(d[0]), "+f"(d[1]), "+f"(d[2]), "+f"(d[3])
        : "r"(a0), "r"(a1), "r"(a2), "r"(a3), "r"(b0), "r"(b1));
}

// ==============================================================================
// 3xBF16 GEMM via mma.sync + cp.async  (exact R8 version — 1147us baseline)
// 128x128 CTA tile, BK=16, 128 threads (4 warps, 64x64 warp tiles).
// ==============================================================================
#define BK     16
#define SSTR   24
#define ST_F   (128 * SSTR)
#define STG_F  (2 * ST_F)
#define NSTG   3
#define TG_SMEM (NSTG * STG_F * 4)  // 73728 B

__global__ __launch_bounds__(128, 2)
void tgemm_bf16_nt_bias(const float* __restrict__ A, const float* __restrict__ B,
                        const float* __restrict__ bias, float* __restrict__ C,
                        int M, int N, int K)
{
    extern __shared__ float sm[];
    const uint32_t smb = smem_u32(sm);

    const int tid  = threadIdx.x;
    const int wid  = tid >> 5;
    const int lane = tid & 31;
    const int qr   = lane >> 2;
    const int qc   = lane & 3;
    const int wm   = (wid & 1) * 64;
    const int wn   = (wid >> 1) * 64;
    const int brow = blockIdx.y * 128;
    const int bcol = blockIdx.x * 128;

    const float* Ag = A + (size_t)(brow + tid) * K;
    const float* Bg = B + (size_t)(bcol + tid) * K;
    const uint32_t dst_off = (uint32_t)(tid * SSTR) * 4;

    const int NT = K / BK;

    auto issue_stage = [&](int kt) {
        const uint32_t da = smb + (uint32_t)((kt % NSTG) * STG_F) * 4 + dst_off;
        const uint32_t db = da + ST_F * 4;
        const float* sa = Ag + kt * BK;
        const float* sb = Bg + kt * BK;
#pragma unroll
        for (int j = 0; j < 4; j++) {
            CP_ASYNC16(da + 16 * j, sa + 4 * j);
            CP_ASYNC16(db + 16 * j, sb + 4 * j);
        }
    };

    float acc[4][8][4];
#pragma unroll
    for (int mt = 0; mt < 4; mt++)
#pragma unroll
        for (int nt = 0; nt < 8; nt++)
#pragma unroll
            for (int i = 0; i < 4; i++) acc[mt][nt][i] = 0.0f;

    issue_stage(0); CP_COMMIT();
    issue_stage(1); CP_COMMIT();

    for (int kt = 0; kt < NT; kt++) {
        CP_WAIT1();
        __syncthreads();

        if (kt + 2 < NT) issue_stage(kt + 2);
        CP_COMMIT();

        const float* As = sm + (kt % NSTG) * STG_F;
        const float* Bs = As + ST_F;

        uint32_t bh[8][2], bl[8][2];
#pragma unroll
        for (int nt = 0; nt < 8; nt++) {
            const int off = (wn + nt * 8 + qr) * SSTR + 2 * qc;
            float2 f = *(const float2*)&Bs[off];
            float2 g = *(const float2*)&Bs[off + 8];
            split2(f.x, f.y, bh[nt][0], bl[nt][0]);
            split2(g.x, g.y, bh[nt][1], bl[nt][1]);
        }
#pragma unroll
        for (int mt = 0; mt < 4; mt++) {
            const int off = (wm + mt * 16 + qr) * SSTR + 2 * qc;
            float2 f0 = *(const float2*)&As[off];
            float2 f1 = *(const float2*)&As[off + 8 * SSTR];
            float2 f2 = *(const float2*)&As[off + 8];
            float2 f3 = *(const float2*)&As[off + 8 * SSTR + 8];
            uint32_t ah0, ah1, ah2, ah3, al0, al1, al2, al3;
            split2(f0.x, f0.y, ah0, al0);
            split2(f1.x, f1.y, ah1, al1);
            split2(f2.x, f2.y, ah2, al2);
            split2(f3.x, f3.y, ah3, al3);
#pragma unroll
            for (int nt = 0; nt < 8; nt++) {
                mma_bf16(acc[mt][nt], ah0, ah1, ah2, ah3, bh[nt][0], bh[nt][1]);
                mma_bf16(acc[mt][nt], ah0, ah1, ah2, ah3, bl[nt][0], bl[nt][1]);
                mma_bf16(acc[mt][nt], al0, al1, al2, al3, bh[nt][0], bh[nt][1]);
            }
        }
        __syncthreads();
    }

#pragma unroll
    for (int mt = 0; mt < 4; mt++) {
        const int row = brow + wm + mt * 16 + qr;
#pragma unroll
        for (int nt = 0; nt < 8; nt++) {
            const int col = bcol + wn + nt * 8 + qc * 2;
            const float b0 = bias[col], b1 = bias[col + 1];
            *(float2*)(C + (size_t)row * N + col) =
                make_float2(acc[mt][nt][0] + b0, acc[mt][nt][1] + b1);
            *(float2*)(C + (size_t)(row + 8) * N + col) =
                make_float2(acc[mt][nt][2] + b0, acc[mt][nt][3] + b1);
        }
    }
}

// ==============================================================================
// RoPE + scale + pack (freq table computed per-block; 32 double-pows per block)
// ==============================================================================
__global__ void ropepack_kernel(const float* __restrict__ X, uint2* __restrict__ out,
                                int H, int istride, int ostride, float scale)
{
    __shared__ float sfreq[32];
    if (threadIdx.x < 32)
        sfreq[threadIdx.x] = (float)pow(10000.0, -(double)threadIdx.x / 32.0);
    __syncthreads();

    int idx = blockIdx.x * blockDim.x + threadIdx.x;
    int total = S_LEN * H * (DH / 2);
    if (idx >= total) return;

    int j = idx & 31;
    int t = idx >> 5;
    int h = t % H;
    int s = t / H;

    float theta = (float)s * sfreq[j];
    float sn, cs;
    sincosf(theta, &sn, &cs);

    const float* p = X + (size_t)s * istride + h * DH + 2 * j;
    float x1 = p[0], x2 = p[1];
    float o1 = (x1 * cs - x2 * sn) * scale;
    float o2 = (x1 * sn + x2 * cs) * scale;
    uint2 o;
    split2(o1, o2, o.x, o.y);
    out[(size_t)s * ostride + h * (DH / 2) + j] = o;
}

// V^T pack: g_Vtp[hk*64+d][sp] = split(V[2sp][hk,d], V[2sp+1][hk,d])
__global__ void vtpack_kernel(const float* __restrict__ KV, uint2* __restrict__ Vt)
{
    int idx = blockIdx.x * blockDim.x + threadIdx.x;   // hk*65536 + d*1024 + sp
    if (idx >= KVH * DH * (S_LEN / 2)) return;
    int sp = idx & (S_LEN / 2 - 1);
    int d  = (idx >> 10) & (DH - 1);
    int hk = idx >> 16;
    const float* base = KV + (size_t)(2 * sp) * KV_W + KVH * DH + hk * DH + d;
    float v0 = base[0];
    float v1 = base[KV_W];
    uint2 o;
    split2(v0, v1, o.x, o.y);
    Vt[idx] = o;
}

// ==============================================================================
// Flash attention (R8 structure, all operands pre-packed; zero fill-path ALU).
// Block = (128 q-rows, head), 128 threads = 4 warps; warp owns 32 rows.
// ==============================================================================
#define AST 36                                   // uint2 row stride
#define OFF_P (128 * AST * 8)                    // 36864
#define OFF_K (2 * OFF_P)                        // 73728
#define OFF_V (OFF_K + 64 * AST * 8)             // 92160
#define FA_SMEM (OFF_V + 64 * AST * 8)           // 110592

__global__ __launch_bounds__(128, 2)
void flash_attn_p(const uint2* __restrict__ Qp, const uint2* __restrict__ Kp,
                  const uint2* __restrict__ Vtp, float* __restrict__ O)
{
    extern __shared__ char smc[];
    uint2* Qsm = (uint2*)smc;
    uint2* Psm = (uint2*)(smc + OFF_P);
    uint2* Ksm = (uint2*)(smc + OFF_K);
    uint2* Vsm = (uint2*)(smc + OFF_V);

    const int qt   = blockIdx.x;
    const int h    = blockIdx.y;
    const int hk   = h >> 2;
    const int tid  = threadIdx.x;
    const int wid  = tid >> 5;
    const int lane = tid & 31;
    const int qr   = lane >> 2;
    const int qc   = lane & 3;
    const int wm   = wid * 32;

    // ---- Q fill: pure packed copy (256 B per row) ----
    {
        const uint2* src = Qp + (size_t)(qt * 128 + tid) * (DM / 2) + h * (DH / 2);
        uint2* dst = Qsm + tid * AST;
#pragma unroll
        for (int j = 0; j < 16; j++)
            *(uint4*)(dst + 2 * j) = *(const uint4*)(src + 2 * j);
    }

    float m_i[2][2], l_i[2][2];
#pragma unroll
    for (int mt = 0; mt < 2; mt++)
#pragma unroll
        for (int hf = 0; hf < 2; hf++) { m_i[mt][hf] = -1e30f; l_i[mt][hf] = 0.0f; }

    float acc[2][8][4];
#pragma unroll
    for (int mt = 0; mt < 2; mt++)
#pragma unroll
        for (int nt = 0; nt < 8; nt++)
#pragma unroll
            for (int i = 0; i < 4; i++) acc[mt][nt][i] = 0.0f;

    for (int kt = 0; kt < 32; kt++) {
        __syncthreads();   // all warps done with previous Ksm/Vsm

        // ---- K + V^T fill: pure packed copies (128 B per thread each) ----
        {
            const int row  = tid >> 1;
            const int half = tid & 1;
            const uint2* kg = Kp + (size_t)(kt * 64 + row) * (KVH * DH / 2) + hk * (DH / 2) + half * 16;
            const uint2* vg = Vtp + (size_t)(hk * 64 + row) * (S_LEN / 2) + kt * 32 + half * 16;
            uint2* kd = Ksm + row * AST + half * 16;
            uint2* vd = Vsm + row * AST + half * 16;
#pragma unroll
            for (int j = 0; j < 8; j++) {
                *(uint4*)(kd + 2 * j) = *(const uint4*)(kg + 2 * j);
                *(uint4*)(vd + 2 * j) = *(const uint4*)(vg + 2 * j);
            }
        }
        __syncthreads();

        // ---- S = Q @ K^T (3xBF16, zero conversions) ----
        float s[2][8][4];
#pragma unroll
        for (int mt = 0; mt < 2; mt++)
#pragma unroll
            for (int nt = 0; nt < 8; nt++)
#pragma unroll
                for (int i = 0; i < 4; i++) s[mt][nt][i] = 0.0f;

#pragma unroll
        for (int ks = 0; ks < 4; ks++) {
            uint2 bk[8][2];
#pragma unroll
            for (int nt = 0; nt < 8; nt++) {
                const int o = (nt * 8 + qr) * AST + ks * 8 + qc;
                bk[nt][0] = Ksm[o];
                bk[nt][1] = Ksm[o + 4];
            }
#pragma unroll
            for (int mt = 0; mt < 2; mt++) {
                const int o = (wm + mt * 16 + qr) * AST + ks * 8 + qc;
                uint2 a0 = Qsm[o];
                uint2 a1 = Qsm[o + 8 * AST];
                uint2 a2 = Qsm[o + 4];
                uint2 a3 = Qsm[o + 8 * AST + 4];
#pragma unroll
                for (int nt = 0; nt < 8; nt++) {
                    mma_bf16(s[mt][nt], a0.x, a1.x, a2.x, a3.x, bk[nt][0].x, bk[nt][1].x);
                    mma_bf16(s[mt][nt], a0.x, a1.x, a2.x, a3.x, bk[nt][0].y, bk[nt][1].y);
                    mma_bf16(s[mt][nt], a0.y, a1.y, a2.y, a3.y, bk[nt][0].x, bk[nt][1].x);
                }
            }
        }

        // ---- online softmax ----
#pragma unroll
        for (int mt = 0; mt < 2; mt++) {
#pragma unroll
            for (int hf = 0; hf < 2; hf++) {
                float mx = -1e30f;
#pragma unroll
                for (int nt = 0; nt < 8; nt++)
                    mx = fmaxf(mx, fmaxf(s[mt][nt][2 * hf], s[mt][nt][2 * hf + 1]));
                mx = fmaxf(mx, __shfl_xor_sync(0xffffffffu, mx, 1));
                mx = fmaxf(mx, __shfl_xor_sync(0xffffffffu, mx, 2));
                float m_new = fmaxf(m_i[mt][hf], mx);
                float alpha = __expf(m_i[mt][hf] - m_new);
                float rs = 0.0f;
#pragma unroll
                for (int nt = 0; nt < 8; nt++) {
                    s[mt][nt][2 * hf]     = __expf(s[mt][nt][2 * hf] - m_new);
                    s[mt][nt][2 * hf + 1] = __expf(s[mt][nt][2 * hf + 1] - m_new);
                    rs += s[mt][nt][2 * hf] + s[mt][nt][2 * hf + 1];
                }
                rs += __shfl_xor_sync(0xffffffffu, rs, 1);
                rs += __shfl_xor_sync(0xffffffffu, rs, 2);
                l_i[mt][hf] = l_i[mt][hf] * alpha + rs;
                m_i[mt][hf] = m_new;
#pragma unroll
                for (int nt = 0; nt < 8; nt++) {
                    acc[mt][nt][2 * hf]     *= alpha;
                    acc[mt][nt][2 * hf + 1] *= alpha;
                }
            }
        }

        // ---- write P packed (warp-private rows) ----
#pragma unroll
        for (int mt = 0; mt < 2; mt++) {
            const int r0 = (wm + mt * 16 + qr) * AST;
#pragma unroll
            for (int nt = 0; nt < 8; nt++) {
                uint2 o;
                split2(s[mt][nt][0], s[mt][nt][1], o.x, o.y);
                Psm[r0 + nt * 4 + qc] = o;
                split2(s[mt][nt][2], s[mt][nt][3], o.x, o.y);
                Psm[r0 + 8 * AST + nt * 4 + qc] = o;
            }
        }
        __syncwarp();

        // ---- acc += P @ V (3xBF16, V^T pre-packed: pure LDS.64) ----
#pragma unroll
        for (int ks = 0; ks < 4; ks++) {
            uint2 bv[8][2];
#pragma unroll
            for (int nt = 0; nt < 8; nt++) {
                const int o = (nt * 8 + qr) * AST + ks * 8 + qc;
                bv[nt][0] = Vsm[o];
                bv[nt][1] = Vsm[o + 4];
            }
#pragma unroll
            for (int mt = 0; mt < 2; mt++) {
                const int o = (wm + mt * 16 + qr) * AST + ks * 8 + qc;
                uint2 p0 = Psm[o];
                uint2 p1 = Psm[o + 8 * AST];
                uint2 p2 = Psm[o + 4];
                uint2 p3 = Psm[o + 8 * AST + 4];
#pragma unroll
                for (int nt = 0; nt < 8; nt++) {
                    mma_bf16(acc[mt][nt], p0.x, p1.x, p2.x, p3.x, bv[nt][0].x, bv[nt][1].x);
                    mma_bf16(acc[mt][nt], p0.x, p1.x, p2.x, p3.x, bv[nt][0].y, bv[nt][1].y);
                    mma_bf16(acc[mt][nt], p0.y, p1.y, p2.y, p3.y, bv[nt][0].x, bv[nt][1].x);
                }
            }
        }
    }

    // ---- epilogue: normalize, store fp32 ----
#pragma unroll
    for (int mt = 0; mt < 2; mt++) {
        const float i0 = 1.0f / l_i[mt][0];
        const float i1 = 1.0f / l_i[mt][1];
        float* d0 = O + (size_t)(qt * 128 + wm + mt * 16 + qr) * DM + h * DH;
        float* d1 = d0 + (size_t)8 * DM;
#pragma unroll
        for (int nt = 0; nt < 8; nt++) {
            *(float2*)(d0 + nt * 8 + 2 * qc) =
                make_float2(acc[mt][nt][0] * i0, acc[mt][nt][1] * i0);
            *(float2*)(d1 + nt * 8 + 2 * qc) =
                make_float2(acc[mt][nt][2] * i1, acc[mt][nt][3] * i1);
        }
    }
}

// ==============================================================================
// launch  (attention is launch index 5 -> ncu -s 5 -c 1 captures it)
// ==============================================================================
extern "C" void kernel_launch(void* const* d_in, const int* in_sizes, int n_in,
                              void* d_out, int out_size)
{
    const float* x     = (const float*)d_in[0];
    const float* W_q   = (const float*)d_in[1];
    const float* b_q   = (const float*)d_in[2];
    const float* W_kv  = (const float*)d_in[3];
    const float* b_kv  = (const float*)d_in[4];
    const float* W_out = (const float*)d_in[5];
    const float* b_out = (const float*)d_in[6];
    float* out = (float*)d_out;

    float *qf, *kvf, *abuf;
    uint2 *qp, *kp, *vtp;
    cudaGetSymbolAddress((void**)&qf,  g_Qf);
    cudaGetSymbolAddress((void**)&kvf, g_KVf);
    cudaGetSymbolAddress((void**)&qp,  g_Qp);
    cudaGetSymbolAddress((void**)&kp,  g_Kp);
    cudaGetSymbolAddress((void**)&vtp, g_Vtp);
    cudaGetSymbolAddress((void**)&abuf, g_attn);

    cudaFuncSetAttribute(flash_attn_p, cudaFuncAttributeMaxDynamicSharedMemorySize, FA_SMEM);
    cudaFuncSetAttribute(tgemm_bf16_nt_bias, cudaFuncAttributeMaxDynamicSharedMemorySize, TG_SMEM);

    // 0: Q projection
    tgemm_bf16_nt_bias<<<dim3(DM / 128, S_LEN / 128), 128, TG_SMEM>>>(
        x, W_q, b_q, qf, S_LEN, DM, DM);
    // 1: KV projection
    tgemm_bf16_nt_bias<<<dim3(KV_W / 128, S_LEN / 128), 128, TG_SMEM>>>(
        x, W_kv, b_kv, kvf, S_LEN, KV_W, DM);

    // 2: rope+scale+pack Q ; 3: rope+pack K ; 4: transpose+pack V
    ropepack_kernel<<<(S_LEN * QH * 32 + 255) / 256, 256>>>(qf, qp, QH, DM, DM / 2, 0.125f);
    ropepack_kernel<<<(S_LEN * KVH * 32 + 255) / 256, 256>>>(kvf, kp, KVH, KV_W, KVH * DH / 2, 1.0f);
    vtpack_kernel<<<(KVH * DH * S_LEN / 2 + 255) / 256, 256>>>(kvf, vtp);

    // 5: flash attention (ncu captures this launch)
    flash_attn_p<<<dim3(S_LEN / 128, QH), 128, FA_SMEM>>>(qp, kp, vtp, abuf);

    // 6: output projection
    tgemm_bf16_nt_bias<<<dim3(DM / 128, S_LEN / 128), 128, TG_SMEM>>>(
        abuf, W_out, b_out, out, S_LEN, DM, DM);
}